// round 4
// baseline (speedup 1.0000x reference)
#include <cuda_runtime.h>
#include <math.h>

#define MAXN 8192
#define THREADS 128
#define QPT 4
#define QBLK (THREADS * QPT)   // 512 queries per block
#define SLAB 512               // DB points per slab (9-bit local index)
#define MAXJB 16               // max DB slabs (8192/512)

// Scratch (allocation-free rule): per-(dir, jblock) partial min keys.
// key = (dist2_bits << 32) | sigma_bits   (both non-negative floats).
__device__ unsigned long long g_pkey[2][MAXJB][MAXN];
__device__ float g_part[64];

// Load point i from a (N,3) array, optionally applying rigid transform rows.
static __device__ __forceinline__ float3 load_pt(const float* __restrict__ P,
                                                 int i, bool xform,
                                                 const float* __restrict__ T) {
    float x = __ldg(&P[3*i]), y = __ldg(&P[3*i+1]), z = __ldg(&P[3*i+2]);
    if (xform) {
        float X = fmaf(T[0], x, fmaf(T[1], y, fmaf(T[2],  z, T[3])));
        float Y = fmaf(T[4], x, fmaf(T[5], y, fmaf(T[6],  z, T[7])));
        float Z = fmaf(T[8], x, fmaf(T[9], y, fmaf(T[10], z, T[11])));
        return make_float3(X, Y, Z);
    }
    return make_float3(x, y, z);
}

// blockIdx.z: 0 => queries=ref, DB=transformed src. 1 => swapped.
// Inner metric d' = |b|^2 - 2 a.b (query-constant |a|^2 dropped: argmin-safe).
// Argmin tracked by embedding j in low 9 mantissa bits + FMNMX (alu pipe).
__global__ void __launch_bounds__(THREADS) nn_kernel(
        const float* __restrict__ ref, const float* __restrict__ src,
        const float* __restrict__ T,
        const float* __restrict__ rsig, const float* __restrict__ ssig,
        int n, int m) {
    const int dir = blockIdx.z;
    const float* Apts = dir ? src : ref;
    const float* Bpts = dir ? ref : src;
    const float* Bsig = dir ? rsig : ssig;
    const int nA = dir ? m : n;
    const int nB = dir ? n : m;
    const bool xformA = (dir == 1), xformB = (dir == 0);

    __shared__ float4 sBt[SLAB];   // (-2x, -2y, -2z, |b|^2)
    __shared__ float4 sBo[SLAB];   // (x, y, z, sigma) for exact epilogue
    const int tid = threadIdx.x;
    const int jbase = blockIdx.y * SLAB;

    for (int j = tid; j < SLAB; j += THREADS) {
        int gj = jbase + j;
        float3 p = (gj < nB) ? load_pt(Bpts, gj, xformB, T)
                             : make_float3(1e15f, 1e15f, 1e15f);
        float s = (gj < nB) ? __ldg(&Bsig[gj]) : 1.0f;
        sBo[j] = make_float4(p.x, p.y, p.z, s);
        float b2 = fmaf(p.x, p.x, fmaf(p.y, p.y, p.z * p.z));
        sBt[j] = make_float4(-2.0f * p.x, -2.0f * p.y, -2.0f * p.z, b2);
    }

    float ax[QPT], ay[QPT], az[QPT], bk[QPT];
    const int q0 = blockIdx.x * QBLK + tid;
#pragma unroll
    for (int q = 0; q < QPT; q++) {
        int qi = q0 + q * THREADS;
        float3 a = (qi < nA) ? load_pt(Apts, qi, xformA, T)
                             : make_float3(0.f, 0.f, 0.f);
        ax[q] = a.x; ay[q] = a.y; az[q] = a.z;
        bk[q] = 3.4e38f;
    }
    __syncthreads();

#pragma unroll 4
    for (int j = 0; j < SLAB; j++) {
        float4 b = sBt[j];   // broadcast LDS.128
#pragma unroll
        for (int q = 0; q < QPT; q++) {
            float d = fmaf(ax[q], b.x, fmaf(ay[q], b.y, fmaf(az[q], b.z, b.w)));
            // embed slab-local index in low 9 mantissa bits (LOP3, alu pipe)
            float kf = __uint_as_float((__float_as_uint(d) & 0xFFFFFE00u) | (unsigned)j);
            bk[q] = fminf(bk[q], kf);   // FMNMX, alu pipe
        }
    }

    // Epilogue: recover index, recompute exact non-negative dist^2, store partial.
#pragma unroll
    for (int q = 0; q < QPT; q++) {
        int qi = q0 + q * THREADS;
        if (qi < nA) {
            int j = (int)(__float_as_uint(bk[q]) & 0x1FFu);
            float4 b = sBo[j];
            float dx = ax[q] - b.x, dy = ay[q] - b.y, dz = az[q] - b.z;
            float d2 = fmaf(dx, dx, fmaf(dy, dy, dz * dz));
            unsigned long long key =
                (((unsigned long long)__float_as_uint(d2)) << 32) |
                (unsigned long long)__float_as_uint(b.w);
            g_pkey[dir][blockIdx.y][qi] = key;   // no atomics
        }
    }
}

// Stage 1: one thread per query (fwd then bwd concatenated); 16-way key min + math.
__global__ void __launch_bounds__(256) reduce1_kernel(
        const float* __restrict__ rsig, const float* __restrict__ ssig,
        int n, int m) {
    __shared__ float wsum[8];
    int idx = blockIdx.x * 256 + threadIdx.x;
    float acc = 0.0f;
    if (idx < n + m) {
        int dir = (idx < n) ? 0 : 1;
        int i = (idx < n) ? idx : idx - n;
        int nB = dir ? n : m;
        int njb = (nB + SLAB - 1) / SLAB;
        unsigned long long k = ~0ULL;
        for (int jb = 0; jb < njb; jb++) {
            unsigned long long v = g_pkey[dir][jb][i];
            k = (v < k) ? v : k;
        }
        float self = dir ? __ldg(&ssig[i]) : __ldg(&rsig[i]);
        float d   = sqrtf(__uint_as_float((unsigned)(k >> 32)));
        float sig = 0.5f * (self + __uint_as_float((unsigned)k));
        float inv = dir ? (1.0f / (float)m) : (1.0f / (float)n);
        acc = (__logf(sig) + __fdividef(d, sig)) * inv;
    }
#pragma unroll
    for (int o = 16; o > 0; o >>= 1)
        acc += __shfl_xor_sync(0xFFFFFFFF, acc, o);
    if ((threadIdx.x & 31) == 0) wsum[threadIdx.x >> 5] = acc;
    __syncthreads();
    if (threadIdx.x < 8) {
        float v = wsum[threadIdx.x];
#pragma unroll
        for (int o = 4; o > 0; o >>= 1)
            v += __shfl_xor_sync(0xFF, v, o);
        if (threadIdx.x == 0) g_part[blockIdx.x] = v;
    }
}

__global__ void reduce2_kernel(float* __restrict__ out, int nblocks) {
    int tid = threadIdx.x;   // 64 threads
    __shared__ float s2[2];
    float v = (tid < nblocks) ? g_part[tid] : 0.0f;
#pragma unroll
    for (int o = 16; o > 0; o >>= 1)
        v += __shfl_xor_sync(0xFFFFFFFF, v, o);
    if ((tid & 31) == 0) s2[tid >> 5] = v;
    __syncthreads();
    if (tid == 0) out[0] = s2[0] + s2[1];
}

extern "C" void kernel_launch(void* const* d_in, const int* in_sizes, int n_in,
                              void* d_out, int out_size) {
    const float* ref  = (const float*)d_in[0];
    const float* src  = (const float*)d_in[1];
    const float* T    = (const float*)d_in[2];
    const float* rsig = (const float*)d_in[3];
    const float* ssig = (const float*)d_in[4];
    int n = in_sizes[3];
    int m = in_sizes[4];

    int nm = n > m ? n : m;
    dim3 g((nm + QBLK - 1) / QBLK, (nm + SLAB - 1) / SLAB, 2);
    nn_kernel<<<g, THREADS>>>(ref, src, T, rsig, ssig, n, m);

    int rblocks = (n + m + 255) / 256;
    reduce1_kernel<<<rblocks, 256>>>(rsig, ssig, n, m);
    reduce2_kernel<<<1, 64>>>((float*)d_out, rblocks);
}

// round 5
// speedup vs baseline: 1.5702x; 1.5702x over previous
#include <cuda_runtime.h>
#include <math.h>

#define MAXN 8192
#define THREADS 256
#define QPT 4
#define QBLK (THREADS * QPT)   // 1024 queries per block
#define SLAB 256               // DB points per slab
#define MAXJB 32               // max DB slabs (8192/256)
#define BIAS 1024.0f           // makes biased metric strictly positive

// Scratch (allocation-free rule): per-(dir, jblock) partial min keys.
// key = (dist2_bits << 32) | sigma_bits   (both non-negative floats).
__device__ unsigned long long g_pkey[2][MAXJB][MAXN];
__device__ float g_part[64];

static __device__ __forceinline__ float3 load_pt(const float* __restrict__ P,
                                                 int i, bool xform,
                                                 const float* __restrict__ T) {
    float x = __ldg(&P[3*i]), y = __ldg(&P[3*i+1]), z = __ldg(&P[3*i+2]);
    if (xform) {
        float X = fmaf(T[0], x, fmaf(T[1], y, fmaf(T[2],  z, T[3])));
        float Y = fmaf(T[4], x, fmaf(T[5], y, fmaf(T[6],  z, T[7])));
        float Z = fmaf(T[8], x, fmaf(T[9], y, fmaf(T[10], z, T[11])));
        return make_float3(X, Y, Z);
    }
    return make_float3(x, y, z);
}

// blockIdx.z: 0 => queries=ref, DB=transformed src. 1 => swapped.
// Metric: d' = BIAS + |b|^2 - 2 a.b  (query-constant |a|^2 dropped: argmin-safe;
// BIAS keeps d' > 0 so float bit patterns order as unsigned ints -> ISETP on alu).
__global__ void __launch_bounds__(THREADS) nn_kernel(
        const float* __restrict__ ref, const float* __restrict__ src,
        const float* __restrict__ T,
        const float* __restrict__ rsig, const float* __restrict__ ssig,
        int n, int m) {
    const int dir = blockIdx.z;
    const float* Apts = dir ? src : ref;
    const float* Bpts = dir ? ref : src;
    const float* Bsig = dir ? rsig : ssig;
    const int nA = dir ? m : n;
    const int nB = dir ? n : m;
    const bool xformA = (dir == 1), xformB = (dir == 0);

    __shared__ float4 sBt[SLAB];   // (-2x, -2y, -2z, |b|^2 + BIAS)
    __shared__ float4 sBo[SLAB];   // (x, y, z, sigma) for exact epilogue
    const int tid = threadIdx.x;
    const int jbase = blockIdx.y * SLAB;

    for (int j = tid; j < SLAB; j += THREADS) {
        int gj = jbase + j;
        float3 p = (gj < nB) ? load_pt(Bpts, gj, xformB, T)
                             : make_float3(1e15f, 1e15f, 1e15f);
        float s = (gj < nB) ? __ldg(&Bsig[gj]) : 1.0f;
        sBo[j] = make_float4(p.x, p.y, p.z, s);
        float b2 = fmaf(p.x, p.x, fmaf(p.y, p.y, p.z * p.z));
        sBt[j] = make_float4(-2.0f * p.x, -2.0f * p.y, -2.0f * p.z, b2 + BIAS);
    }

    float ax[QPT], ay[QPT], az[QPT];
    unsigned bk[QPT];
    int bj[QPT];
    const int q0 = blockIdx.x * QBLK + tid;
#pragma unroll
    for (int q = 0; q < QPT; q++) {
        int qi = q0 + q * THREADS;
        float3 a = (qi < nA) ? load_pt(Apts, qi, xformA, T)
                             : make_float3(0.f, 0.f, 0.f);
        ax[q] = a.x; ay[q] = a.y; az[q] = a.z;
        bk[q] = 0xFFFFFFFFu; bj[q] = 0;
    }
    __syncthreads();

#pragma unroll 4
    for (int j = 0; j < SLAB; j++) {
        float4 b = sBt[j];   // broadcast LDS.128 (j uniform across warp)
#pragma unroll
        for (int q = 0; q < QPT; q++) {
            float d = fmaf(ax[q], b.x, fmaf(ay[q], b.y, fmaf(az[q], b.z, b.w)));
            unsigned di = __float_as_uint(d);   // free reinterpret
            if (di < bk[q]) { bk[q] = di; bj[q] = j; }   // ISETP.U32 + 2 SEL (alu)
        }
    }

    // Epilogue: exact non-negative dist^2 for the winner, pack with its sigma.
#pragma unroll
    for (int q = 0; q < QPT; q++) {
        int qi = q0 + q * THREADS;
        if (qi < nA) {
            float4 b = sBo[bj[q]];
            float dx = ax[q] - b.x, dy = ay[q] - b.y, dz = az[q] - b.z;
            float d2 = fmaf(dx, dx, fmaf(dy, dy, dz * dz));
            unsigned long long key =
                (((unsigned long long)__float_as_uint(d2)) << 32) |
                (unsigned long long)__float_as_uint(b.w);
            g_pkey[dir][blockIdx.y][qi] = key;   // no atomics
        }
    }
}

// Stage 1: one thread per query (fwd then bwd concatenated); scan slab partials.
__global__ void __launch_bounds__(256) reduce1_kernel(
        const float* __restrict__ rsig, const float* __restrict__ ssig,
        int n, int m) {
    __shared__ float wsum[8];
    int idx = blockIdx.x * 256 + threadIdx.x;
    float acc = 0.0f;
    if (idx < n + m) {
        int dir = (idx < n) ? 0 : 1;
        int i = (idx < n) ? idx : idx - n;
        int nB = dir ? n : m;
        int njb = (nB + SLAB - 1) / SLAB;
        unsigned long long k = ~0ULL;
        for (int jb = 0; jb < njb; jb++) {
            unsigned long long v = g_pkey[dir][jb][i];
            k = (v < k) ? v : k;
        }
        float self = dir ? __ldg(&ssig[i]) : __ldg(&rsig[i]);
        float d   = sqrtf(__uint_as_float((unsigned)(k >> 32)));
        float sig = 0.5f * (self + __uint_as_float((unsigned)k));
        float inv = dir ? (1.0f / (float)m) : (1.0f / (float)n);
        acc = (__logf(sig) + __fdividef(d, sig)) * inv;
    }
#pragma unroll
    for (int o = 16; o > 0; o >>= 1)
        acc += __shfl_xor_sync(0xFFFFFFFF, acc, o);
    if ((threadIdx.x & 31) == 0) wsum[threadIdx.x >> 5] = acc;
    __syncthreads();
    if (threadIdx.x < 8) {
        float v = wsum[threadIdx.x];
#pragma unroll
        for (int o = 4; o > 0; o >>= 1)
            v += __shfl_xor_sync(0xFF, v, o);
        if (threadIdx.x == 0) g_part[blockIdx.x] = v;
    }
}

__global__ void reduce2_kernel(float* __restrict__ out, int nblocks) {
    int tid = threadIdx.x;   // 64 threads
    __shared__ float s2[2];
    float v = (tid < nblocks) ? g_part[tid] : 0.0f;
#pragma unroll
    for (int o = 16; o > 0; o >>= 1)
        v += __shfl_xor_sync(0xFFFFFFFF, v, o);
    if ((tid & 31) == 0) s2[tid >> 5] = v;
    __syncthreads();
    if (tid == 0) out[0] = s2[0] + s2[1];
}

extern "C" void kernel_launch(void* const* d_in, const int* in_sizes, int n_in,
                              void* d_out, int out_size) {
    const float* ref  = (const float*)d_in[0];
    const float* src  = (const float*)d_in[1];
    const float* T    = (const float*)d_in[2];
    const float* rsig = (const float*)d_in[3];
    const float* ssig = (const float*)d_in[4];
    int n = in_sizes[3];
    int m = in_sizes[4];

    int nm = n > m ? n : m;
    dim3 g((nm + QBLK - 1) / QBLK, (nm + SLAB - 1) / SLAB, 2);
    nn_kernel<<<g, THREADS>>>(ref, src, T, rsig, ssig, n, m);

    int rblocks = (n + m + 255) / 256;
    reduce1_kernel<<<rblocks, 256>>>(rsig, ssig, n, m);
    reduce2_kernel<<<1, 64>>>((float*)d_out, rblocks);
}